// round 13
// baseline (speedup 1.0000x reference)
#include <cuda_runtime.h>
#include <cuda_fp16.h>

#define IMGN 256
#define NANG 512
#define NB   4
#define QW   257          // quad texture width (1-px zero border)
#define QSZ  (QW * QW)

// Batch-pair-interleaved fp16 quad textures, 16B per sample point per pair:
//   { half2(t00,t01) b_even, half2(t10,t11) b_even, half2(t00,t01) b_odd, half2(t10,t11) b_odd }
// taps t00=(m0,n0) t01=(m0,n1) t10=(m1,n0) t11=(m1,n1); m = major axis of plane.
// Normal planes: m=y, n=x (idx = yi*QW+xi). Transposed planes: m=x, n=y.
__device__ uint4 g_texA [QSZ];   // batches 0,1  normal
__device__ uint4 g_texB [QSZ];   // batches 2,3  normal
__device__ uint4 g_texAT[QSZ];   // batches 0,1  transposed
__device__ uint4 g_texBT[QSZ];   // batches 2,3  transposed

__device__ __forceinline__ unsigned pack2(float lo, float hi) {
    __half2 h = __floats2half2_rn(lo, hi);
    return *reinterpret_cast<unsigned*>(&h);
}
__device__ __forceinline__ float2 unpack2(unsigned u) {
    __half2 h = *reinterpret_cast<__half2*>(&u);
    return __half22float2(h);
}

__global__ void radon_prep(const float* __restrict__ img) {
    int tid = blockIdx.x * blockDim.x + threadIdx.x;
    if (tid >= QSZ) return;
    int mi = tid / QW, ni = tid - mi * QW;
    int y0 = mi - 1, x0 = ni - 1;

    float t[NB][4];
    #pragma unroll
    for (int b = 0; b < NB; b++) {
        const float* im = img + b * IMGN * IMGN;
        bool y0k = (unsigned)y0 < IMGN, y1k = (unsigned)(y0 + 1) < IMGN;
        bool x0k = (unsigned)x0 < IMGN, x1k = (unsigned)(x0 + 1) < IMGN;
        t[b][0] = (y0k && x0k) ? im[y0 * IMGN + x0]           : 0.f;
        t[b][1] = (y0k && x1k) ? im[y0 * IMGN + x0 + 1]       : 0.f;
        t[b][2] = (y1k && x0k) ? im[(y0 + 1) * IMGN + x0]     : 0.f;
        t[b][3] = (y1k && x1k) ? im[(y0 + 1) * IMGN + x0 + 1] : 0.f;
    }
    // normal: m=y -> taps in order (t0,t1 | t2,t3)
    g_texA[tid] = make_uint4(pack2(t[0][0], t[0][1]), pack2(t[0][2], t[0][3]),
                             pack2(t[1][0], t[1][1]), pack2(t[1][2], t[1][3]));
    g_texB[tid] = make_uint4(pack2(t[2][0], t[2][1]), pack2(t[2][2], t[2][3]),
                             pack2(t[3][0], t[3][1]), pack2(t[3][2], t[3][3]));
    // transposed: m=x -> t00=tap0, t01=tap2, t10=tap1, t11=tap3
    int tidT = ni * QW + mi;
    g_texAT[tidT] = make_uint4(pack2(t[0][0], t[0][2]), pack2(t[0][1], t[0][3]),
                               pack2(t[1][0], t[1][2]), pack2(t[1][1], t[1][3]));
    g_texBT[tidT] = make_uint4(pack2(t[2][0], t[2][2]), pack2(t[2][1], t[2][3]),
                               pack2(t[3][0], t[3][2]), pack2(t[3][1], t[3][3]));
}

// grid: (NANG, 4). block: 256 threads = 8 warps.
// warp covers 8 detector positions (wloc) x 4 h-phases (hg); lane h-stride = 4.
__global__ void __launch_bounds__(256) radon_main(float* __restrict__ out) {
    const int a    = blockIdx.x;
    const int lane = threadIdx.x & 31;
    const int wloc = lane & 7;
    const int hg   = lane >> 3;
    const int w    = blockIdx.y * 64 + (threadIdx.x >> 5) * 8 + wloc;

    // theta = a*pi/512 exactly; sinpif/cospif on exact dyadic argument
    float fa = (float)a * (1.0f / 512.0f);
    float s = sinpif(fa);           // >= 0 for a in [0,512)
    float c = cospif(fa);

    const float sc = 0.5f * (IMGN - 1);
    const float wc = (float)w - sc;
    const float Ax = c * wc - s * sc + sc;   // fx(h) = Ax + s*h
    const float By = -s * wc - c * sc + sc;  // fy(h) = By + c*h

    // Clip ray to fx,fy in [-1, 256)
    float lo = 0.f, hi = 255.f;
    const float EPS = 1e-6f;
    if (s > EPS) {
        float inv = 1.f / s;
        lo = fmaxf(lo, (-1.f - Ax) * inv);
        hi = fminf(hi, (256.f - Ax) * inv);
    } else if (Ax < -1.f || Ax >= 256.f) hi = -2.f;
    if (c > EPS) {
        float inv = 1.f / c;
        lo = fmaxf(lo, (-1.f - By) * inv);
        hi = fminf(hi, (256.f - By) * inv);
    } else if (c < -EPS) {
        float inv = 1.f / c;
        lo = fmaxf(lo, (256.f - By) * inv);
        hi = fminf(hi, (-1.f - By) * inv);
    } else if (By < -1.f || By >= 256.f) hi = -2.f;

    int h0 = max(0, (int)floorf(lo) - 1);
    int h1 = min(IMGN - 1, (int)ceilf(hi) + 1);

    // Per-angle plane/axis selection: major axis = the one with the larger lane-delta.
    bool tr = (fabsf(c) < s);
    const uint4* __restrict__ pA = tr ? g_texAT : g_texA;
    const uint4* __restrict__ pB = tr ? g_texBT : g_texB;
    float Fm, dm, Fn, dn;
    if (tr) { Fm = Ax; dm = s; Fn = By; dn = c; }
    else    { Fm = By; dm = c; Fn = Ax; dn = s; }

    // this lane samples h = hg + 4*k
    int tlo = h0 - hg;
    int k0 = (tlo <= 0) ? 0 : ((tlo + 3) >> 2);
    int k1 = (h1 - hg) >> 2;                  // arithmetic shift: empty if negative

    float acc0 = 0.f, acc1 = 0.f, acc2 = 0.f, acc3 = 0.f;
    float hf = (float)(hg + 4 * k0);          // exact integer-valued float

    #pragma unroll 4
    for (int k = k0; k <= k1; ++k) {
        float fm = fmaf(dm, hf, Fm);
        float fn = fmaf(dn, hf, Fn);
        hf += 4.0f;
        float mf = floorf(fm), nf = floorf(fn);
        int mi = (int)mf + 1, ni = (int)nf + 1;
        if (max((unsigned)mi, (unsigned)ni) <= 256u) {
            float wm = fm - mf, wn = fn - nf;
            float wm0 = 1.f - wm, wn0 = 1.f - wn;
            float w00 = wm0 * wn0, w01 = wm0 * wn;
            float w10 = wm  * wn0, w11 = wm  * wn;
            int idx = mi * QW + ni;
            uint4 qa = __ldg(pA + idx);
            uint4 qb = __ldg(pB + idx);
            float2 a0 = unpack2(qa.x), a1 = unpack2(qa.y);
            float2 b0 = unpack2(qa.z), b1 = unpack2(qa.w);
            float2 c0 = unpack2(qb.x), c1 = unpack2(qb.y);
            float2 d0 = unpack2(qb.z), d1 = unpack2(qb.w);
            acc0 = fmaf(a0.x, w00, fmaf(a0.y, w01, fmaf(a1.x, w10, fmaf(a1.y, w11, acc0))));
            acc1 = fmaf(b0.x, w00, fmaf(b0.y, w01, fmaf(b1.x, w10, fmaf(b1.y, w11, acc1))));
            acc2 = fmaf(c0.x, w00, fmaf(c0.y, w01, fmaf(c1.x, w10, fmaf(c1.y, w11, acc2))));
            acc3 = fmaf(d0.x, w00, fmaf(d0.y, w01, fmaf(d1.x, w10, fmaf(d1.y, w11, acc3))));
        }
    }

    // combine the 4 h-phases (lanes sharing wloc)
    acc0 += __shfl_xor_sync(0xffffffffu, acc0, 8);
    acc0 += __shfl_xor_sync(0xffffffffu, acc0, 16);
    acc1 += __shfl_xor_sync(0xffffffffu, acc1, 8);
    acc1 += __shfl_xor_sync(0xffffffffu, acc1, 16);
    acc2 += __shfl_xor_sync(0xffffffffu, acc2, 8);
    acc2 += __shfl_xor_sync(0xffffffffu, acc2, 16);
    acc3 += __shfl_xor_sync(0xffffffffu, acc3, 8);
    acc3 += __shfl_xor_sync(0xffffffffu, acc3, 16);

    // lane's hg selects which batch it stores: out[(b*IMGN + w)*NANG + a]
    float v = acc0;
    if (hg == 1) v = acc1;
    else if (hg == 2) v = acc2;
    else if (hg == 3) v = acc3;
    out[(hg * IMGN + w) * NANG + a] = v;
}

extern "C" void kernel_launch(void* const* d_in, const int* in_sizes, int n_in,
                              void* d_out, int out_size) {
    const float* img = (const float*)d_in[0];
    float* out = (float*)d_out;

    radon_prep<<<(QSZ + 255) / 256, 256>>>(img);
    dim3 grid(NANG, 4);
    radon_main<<<grid, 256>>>(out);
}